// round 8
// baseline (speedup 1.0000x reference)
#include <cuda_runtime.h>
#include <cuda_fp16.h>
#include <math.h>
#include <stdint.h>

// Problem constants
#define MFFT 8192      // complex FFT size (packed real of N=16384)
#define MH   4096      // MFFT/2
#define LOGM 13
#define HDIM 512
#define BDIM 8
#define LDIM 8192

// Padded smem indexing: one extra float2 slot per 16 -> breaks small-stride
// bank-conflict uniformity. Max index 8191 -> 8702; array 8704 float2 = 68KB.
#define IDX(a) ((a) + ((a) >> 4))
#define APAD 8704

// Device scratch
__device__ float2   g_Kf[HDIM * 8193];                  // rfft(k, 16384) per h
__device__ uint32_t g_P[(size_t)BDIM * HDIM * LDIM];    // gelu result, fp16 (h, h) duplicated
__device__ uint32_t g_Wp[HDIM * HDIM];                  // W fp16 (hi, lo) split

__device__ __forceinline__ float2 cmulf2(float2 a, float2 b) {
    return make_float2(a.x * b.x - a.y * b.y, a.x * b.y + a.y * b.x);
}
__device__ __forceinline__ float2 caddf2(float2 a, float2 b) { return make_float2(a.x + b.x, a.y + b.y); }
__device__ __forceinline__ float2 csubf2(float2 a, float2 b) { return make_float2(a.x - b.x, a.y - b.y); }
__device__ __forceinline__ float2 conjf2(float2 a) { return make_float2(a.x, -a.y); }
__device__ __forceinline__ int rev13(int k) { return (int)(__brev((unsigned)k) >> 19); }

__device__ __forceinline__ uint32_t pack_w(float v) {
    __half h = __float2half_rn(v);
    __half l = __float2half_rn(v - __half2float(h));
    return (uint32_t)__half_as_ushort(h) | ((uint32_t)__half_as_ushort(l) << 16);
}
__device__ __forceinline__ uint32_t pack_g(float v) {
    uint32_t h = (uint32_t)__half_as_ushort(__float2half_rn(v));
    return h | (h << 16);
}

// Fused double radix-2 DIF passes: natural input -> bit-reversed output.
__device__ void fft_forward(float2* A, int tid) {
#pragma unroll
    for (int s = 0; s < 12; s += 2) {
        int ld2 = 11 - s;
        int d2 = 1 << ld2;
        int d1 = d2 << 1;
        __syncthreads();
#pragma unroll
        for (int p = 0; p < 4; p++) {
            int g = tid + p * 512;
            int tw = g & (d2 - 1);
            int i = ((g >> ld2) << (ld2 + 2)) + tw;
            float2 a0 = A[IDX(i)], a1 = A[IDX(i + d2)], a2 = A[IDX(i + d1)], a3 = A[IDX(i + d1 + d2)];
            float ang = (-6.283185307179586f / 8192.0f) * (float)(tw << s);
            float sn, cs; __sincosf(ang, &sn, &cs);
            float2 w1 = make_float2(cs, sn);
            float2 w2 = cmulf2(w1, w1);
            float2 s02 = caddf2(a0, a2), d02 = csubf2(a0, a2);
            float2 s13 = caddf2(a1, a3), d13 = csubf2(a1, a3);
            A[IDX(i)]      = caddf2(s02, s13);
            A[IDX(i + d2)] = cmulf2(csubf2(s02, s13), w2);
            float2 m  = make_float2(d02.x + d13.y, d02.y - d13.x);
            A[IDX(i + d1)] = cmulf2(m, w1);
            float2 pq = make_float2(d02.x - d13.y, d02.y + d13.x);
            A[IDX(i + d1 + d2)] = cmulf2(cmulf2(pq, w1), w2);
        }
    }
    __syncthreads();
#pragma unroll
    for (int p = 0; p < 8; p++) {
        int j = tid + p * 512;
        float2 a = A[IDX(2 * j)], b = A[IDX(2 * j + 1)];
        A[IDX(2 * j)]     = caddf2(a, b);
        A[IDX(2 * j + 1)] = csubf2(a, b);
    }
    __syncthreads();
}

// Fused double radix-2 DIT passes (conjugate twiddles): bit-reversed -> natural.
__device__ void fft_inverse(float2* A, int tid) {
    __syncthreads();
#pragma unroll
    for (int p = 0; p < 8; p++) {
        int j = tid + p * 512;
        float2 a = A[IDX(2 * j)], b = A[IDX(2 * j + 1)];
        A[IDX(2 * j)]     = caddf2(a, b);
        A[IDX(2 * j + 1)] = csubf2(a, b);
    }
#pragma unroll
    for (int s = 1; s < 13; s += 2) {
        int d1 = 1 << s;
        int d2 = d1 << 1;
        __syncthreads();
#pragma unroll
        for (int p = 0; p < 4; p++) {
            int g = tid + p * 512;
            int tw = g & (d1 - 1);
            int i = ((g >> s) << (s + 2)) + tw;
            float2 a0 = A[IDX(i)], a1 = A[IDX(i + d1)], a2 = A[IDX(i + d2)], a3 = A[IDX(i + d1 + d2)];
            float ang = (6.283185307179586f / 8192.0f) * (float)(tw << (11 - s));
            float sn, cs; __sincosf(ang, &sn, &cs);
            float2 v0 = make_float2(cs, sn);
            float2 w  = cmulf2(v0, v0);
            float2 t1 = cmulf2(a1, w);
            float2 t3 = cmulf2(a3, w);
            float2 b0 = caddf2(a0, t1), b1 = csubf2(a0, t1);
            float2 b2 = caddf2(a2, t3), b3 = csubf2(a2, t3);
            float2 e  = cmulf2(b2, v0);
            float2 f  = cmulf2(b3, v0);
            A[IDX(i)]           = caddf2(b0, e);
            A[IDX(i + d2)]      = csubf2(b0, e);
            A[IDX(i + d1)]      = make_float2(b1.x - f.y, b1.y + f.x);
            A[IDX(i + d1 + d2)] = make_float2(b1.x + f.y, b1.y - f.x);
        }
    }
    __syncthreads();
}

// Kernel A: Kf[h] = rfft(k[h], 16384)
extern "C" __global__ void __launch_bounds__(512) kf_kernel(const float* __restrict__ kin) {
    extern __shared__ float2 sh[];
    float2* A = sh;
    int tid = threadIdx.x;
    int h = blockIdx.x;
    const float2* kp = (const float2*)(kin + (size_t)h * LDIM);
    for (int j = tid; j < MH; j += 512) {
        A[IDX(j)] = kp[j];
        A[IDX(j + MH)] = make_float2(0.f, 0.f);
    }
    fft_forward(A, tid);
    float2* outp = g_Kf + (size_t)h * 8193;
    for (int k = tid; k < MH; k += 512) {
        if (k == 0) {
            float2 Z0 = A[IDX(0)];
            outp[0]    = make_float2(Z0.x + Z0.y, 0.f);
            outp[8192] = make_float2(Z0.x - Z0.y, 0.f);
            outp[4096] = conjf2(A[IDX(1)]);
        } else {
            float2 Zk = A[IDX(rev13(k))];
            float2 Zm = A[IDX(rev13(MFFT - k))];
            float2 cZm = conjf2(Zm);
            float2 E  = make_float2(0.5f * (Zk.x + cZm.x), 0.5f * (Zk.y + cZm.y));
            float2 Dd = csubf2(Zk, cZm);
            float2 O  = make_float2(0.5f * Dd.y, -0.5f * Dd.x);
            float ang = (-3.14159265358979323846f / 8192.0f) * (float)k;
            float sn, cs; __sincosf(ang, &sn, &cs);
            float2 Wt = make_float2(cs, sn);
            float2 WO = cmulf2(Wt, O);
            outp[k]        = caddf2(E, WO);
            outp[MFFT - k] = conjf2(csubf2(E, WO));
        }
    }
}

// Kernel B: conv + skip + gelu -> fp16 (h,h) words
extern "C" __global__ void __launch_bounds__(512) conv_kernel(
    const float* __restrict__ u, const float* __restrict__ Dv) {
    extern __shared__ float2 sh[];
    float2* A = sh;
    int tid = threadIdx.x;
    int b = blockIdx.x & (BDIM - 1);
    int h = blockIdx.x >> 3;
    const float2* up = (const float2*)(u + ((size_t)b * HDIM + h) * LDIM);
    for (int j = tid; j < MH; j += 512) {
        A[IDX(j)] = up[j];
        A[IDX(j + MH)] = make_float2(0.f, 0.f);
    }
    fft_forward(A, tid);

    const float2* Kf = g_Kf + (size_t)h * 8193;
    for (int k = tid; k < MH; k += 512) {
        if (k == 0) {
            float2 Z0 = A[IDX(0)];
            float X0 = Z0.x + Z0.y;
            float XM = Z0.x - Z0.y;
            float2 K0 = Kf[0], KM = Kf[8192];
            float2 Y0 = make_float2(X0 * K0.x, X0 * K0.y);
            float2 YM = make_float2(XM * KM.x, XM * KM.y);
            float2 cYM = conjf2(YM);
            float2 Ep = make_float2(0.5f * (Y0.x + cYM.x), 0.5f * (Y0.y + cYM.y));
            float2 Op = make_float2(0.5f * (Y0.x - cYM.x), 0.5f * (Y0.y - cYM.y));
            A[IDX(0)] = make_float2(Ep.x - Op.y, Ep.y + Op.x);
            float2 Zq = A[IDX(1)];
            float2 Yq = cmulf2(conjf2(Zq), Kf[4096]);
            A[IDX(1)] = conjf2(Yq);
        } else {
            int rk = rev13(k), rm = rev13(MFFT - k);
            float2 Zk = A[IDX(rk)], Zm = A[IDX(rm)];
            float2 cZm = conjf2(Zm);
            float2 E  = make_float2(0.5f * (Zk.x + cZm.x), 0.5f * (Zk.y + cZm.y));
            float2 Dd = csubf2(Zk, cZm);
            float2 O  = make_float2(0.5f * Dd.y, -0.5f * Dd.x);
            float ang = (-3.14159265358979323846f / 8192.0f) * (float)k;
            float sn, cs; __sincosf(ang, &sn, &cs);
            float2 Wt = make_float2(cs, sn);
            float2 WO = cmulf2(Wt, O);
            float2 Xk = caddf2(E, WO);
            float2 Xm = conjf2(csubf2(E, WO));
            float2 Yk = cmulf2(Xk, Kf[k]);
            float2 Ym = cmulf2(Xm, Kf[MFFT - k]);
            float2 cYm = conjf2(Ym);
            float2 Ep = make_float2(0.5f * (Yk.x + cYm.x), 0.5f * (Yk.y + cYm.y));
            float2 P  = make_float2(0.5f * (Yk.x - cYm.x), 0.5f * (Yk.y - cYm.y));
            float2 Op = cmulf2(conjf2(Wt), P);
            A[IDX(rk)] = make_float2(Ep.x - Op.y, Ep.y + Op.x);
            A[IDX(rm)] = make_float2(Ep.x + Op.y, Op.x - Ep.y);
        }
    }
    fft_inverse(A, tid);

    float Dh = Dv[h];
    uint2* gp = (uint2*)(g_P + ((size_t)b * HDIM + h) * LDIM);
    const float inv = 1.0f / (float)MFFT;
    for (int j = tid; j < MH; j += 512) {
        float2 z = A[IDX(j)];
        float2 uu = up[j];
        float y0 = z.x * inv + Dh * uu.x;
        float y1 = z.y * inv + Dh * uu.y;
        float g0 = 0.5f * y0 * (1.0f + erff(y0 * 0.70710678118654752440f));
        float g1 = 0.5f * y1 * (1.0f + erff(y1 * 0.70710678118654752440f));
        gp[j] = make_uint2(pack_g(g0), pack_g(g1));
    }
}

// W pack kernel
extern "C" __global__ void __launch_bounds__(256) wpack_kernel(const float* __restrict__ Wm) {
    int i = blockIdx.x * 256 + threadIdx.x;
    g_Wp[i] = pack_w(Wm[i]);
}

// ---------------- mma.sync GEMM, 3-stage cp.async pipeline (R7, kept) ----------------
__device__ __forceinline__ uint32_t smem_u32(const void* p) {
    return (uint32_t)__cvta_generic_to_shared(p);
}
__device__ __forceinline__ uint32_t swz(uint32_t off) { return off ^ ((off >> 3) & 0x70); }

__device__ __forceinline__ void ldmat4(uint32_t* r, uint32_t addr) {
    asm volatile("ldmatrix.sync.aligned.m8n8.x4.shared.b16 {%0,%1,%2,%3}, [%4];"
                 : "=r"(r[0]), "=r"(r[1]), "=r"(r[2]), "=r"(r[3]) : "r"(addr));
}
__device__ __forceinline__ void mma16816(float* d, const uint32_t* a, uint32_t b0, uint32_t b1) {
    asm volatile(
        "mma.sync.aligned.m16n8k16.row.col.f32.f16.f16.f32 "
        "{%0,%1,%2,%3}, {%4,%5,%6,%7}, {%8,%9}, {%0,%1,%2,%3};"
        : "+f"(d[0]), "+f"(d[1]), "+f"(d[2]), "+f"(d[3])
        : "r"(a[0]), "r"(a[1]), "r"(a[2]), "r"(a[3]), "r"(b0), "r"(b1));
}
#define CP16(dst, src) asm volatile("cp.async.cg.shared.global [%0], [%1], 16;" :: "r"(dst), "l"(src) : "memory")
#define CP4(dst, src)  asm volatile("cp.async.ca.shared.global [%0], [%1], 4;"  :: "r"(dst), "l"(src) : "memory")
#define CP_COMMIT()    asm volatile("cp.async.commit_group;" ::: "memory")
#define CP_WAIT1()     asm volatile("cp.async.wait_group 1;" ::: "memory")

extern "C" __global__ void __launch_bounds__(256, 2) gemm_mma_kernel(
    const float* __restrict__ bias, float* __restrict__ outp) {
    extern __shared__ char smem[];
    uint32_t sb = smem_u32(smem);
    int t = threadIdx.x;
    int lane = t & 31, wid = t >> 5;
    int warp_m = wid >> 2, warp_n = wid & 3;   // 2 x 4 warp grid; warp tile 64x32
    int o0 = blockIdx.x * 128, l0 = blockIdx.y * 128, b = blockIdx.z;

    int a_row = t >> 1, a_half = t & 1;
    const uint32_t* wp = g_Wp + (size_t)(o0 + a_row) * HDIM + a_half * 16;
    int b_l = t & 127, b_hg = (t >> 7) * 16;
    const uint32_t* gpB = g_P + (size_t)b * HDIM * LDIM + l0 + b_l;

    auto load_chunk = [&](int c) {
        int buf = c % 3;
        uint32_t sA = sb + buf * 32768;
        uint32_t sB = sA + 16384;
        const uint32_t* aw = wp + c * 32;
#pragma unroll
        for (int j = 0; j < 4; j++) {
            uint32_t off = (uint32_t)(a_row * 128 + (a_half * 16 + j * 4) * 4);
            CP16(sA + swz(off), aw + j * 4);
        }
#pragma unroll
        for (int q = 0; q < 16; q++) {
            int hw = b_hg + q;
            uint32_t off = (uint32_t)(b_l * 128 + hw * 4);
            CP4(sB + swz(off), gpB + (size_t)(c * 32 + hw) * LDIM);
        }
    };

    int a_lrow = (lane & 7) + ((lane >> 3) & 1) * 8;
    int a_lcol = (lane >> 4) * 16;
    int b_lrow = (lane & 7) + ((lane >> 4) & 1) * 8;
    int b_lcol = ((lane >> 3) & 1) * 16;
    uint32_t xorm = (uint32_t)((lane & 7) << 4);

    float acc[4][4][4];
#pragma unroll
    for (int i = 0; i < 4; i++)
#pragma unroll
        for (int j = 0; j < 4; j++)
#pragma unroll
            for (int q = 0; q < 4; q++) acc[i][j][q] = 0.f;

    load_chunk(0);
    CP_COMMIT();
    load_chunk(1);
    CP_COMMIT();

#pragma unroll 1
    for (int c = 0; c < 16; c++) {
        CP_WAIT1();
        __syncthreads();
        if (c + 2 < 16) load_chunk(c + 2);
        CP_COMMIT();
        int buf = c % 3;
        uint32_t sA = sb + buf * 32768;
        uint32_t sB = sA + 16384;
#pragma unroll
        for (int s = 0; s < 4; s++) {
            uint32_t afr[4][4];
#pragma unroll
            for (int mt = 0; mt < 4; mt++) {
                uint32_t off = (uint32_t)((warp_m * 64 + mt * 16 + a_lrow) * 128 + s * 32 + a_lcol);
                ldmat4(afr[mt], sA + (off ^ xorm));
            }
#pragma unroll
            for (int bt = 0; bt < 2; bt++) {
                uint32_t bfr[4];
                uint32_t off = (uint32_t)((warp_n * 32 + bt * 16 + b_lrow) * 128 + s * 32 + b_lcol);
                ldmat4(bfr, sB + (off ^ xorm));
#pragma unroll
                for (int mt = 0; mt < 4; mt++) {
                    mma16816(acc[mt][bt * 2 + 0], afr[mt], bfr[0], bfr[1]);
                    mma16816(acc[mt][bt * 2 + 1], afr[mt], bfr[2], bfr[3]);
                }
            }
        }
    }

#pragma unroll
    for (int mt = 0; mt < 4; mt++) {
        int r = o0 + warp_m * 64 + mt * 16 + (lane >> 2);
        float bs0 = bias[r], bs1 = bias[r + 8];
        float* p0 = outp + ((size_t)b * HDIM + r) * LDIM + l0 + warp_n * 32 + (lane & 3) * 2;
        float* p1 = p0 + 8 * LDIM;
#pragma unroll
        for (int nt = 0; nt < 4; nt++) {
            float2 v0 = make_float2(acc[mt][nt][0] + bs0, acc[mt][nt][1] + bs0);
            float2 v1 = make_float2(acc[mt][nt][2] + bs1, acc[mt][nt][3] + bs1);
            *(float2*)(p0 + nt * 8) = v0;
            *(float2*)(p1 + nt * 8) = v1;
        }
    }
}

extern "C" void kernel_launch(void* const* d_in, const int* in_sizes, int n_in,
                              void* d_out, int out_size) {
    const float* u    = (const float*)d_in[0];   // (8,512,8192)
    const float* kin  = (const float*)d_in[1];   // (1,512,8192)
    const float* Dv   = (const float*)d_in[2];   // (1,512)
    const float* Wm   = (const float*)d_in[3];   // (512,512)
    const float* bias = (const float*)d_in[4];   // (512,)
    float* outp = (float*)d_out;                 // (8,512,8192)

    size_t smem = (size_t)APAD * sizeof(float2);  // 68 KB (padded)
    cudaFuncSetAttribute(kf_kernel,   cudaFuncAttributeMaxDynamicSharedMemorySize, (int)smem);
    cudaFuncSetAttribute(conv_kernel, cudaFuncAttributeMaxDynamicSharedMemorySize, (int)smem);
    size_t gsmem = 3 * 32768;                      // 96 KB (3-stage)
    cudaFuncSetAttribute(gemm_mma_kernel, cudaFuncAttributeMaxDynamicSharedMemorySize, (int)gsmem);

    wpack_kernel<<<HDIM * HDIM / 256, 256>>>(Wm);
    kf_kernel<<<HDIM, 512, smem>>>(kin);
    conv_kernel<<<BDIM * HDIM, 512, smem>>>(u, Dv);
    dim3 grid(HDIM / 128, LDIM / 128, BDIM);      // o fastest -> B-panel L2 reuse
    gemm_mma_kernel<<<grid, 256, gsmem>>>(bias, outp);
}

// round 9
// speedup vs baseline: 1.1730x; 1.1730x over previous
#include <cuda_runtime.h>
#include <cuda_fp16.h>
#include <math.h>
#include <stdint.h>

// Problem constants
#define MFFT 8192      // complex FFT size (packed real of N=16384)
#define MH   4096      // MFFT/2
#define LOGM 13
#define HDIM 512
#define BDIM 8
#define LDIM 8192

// Device scratch
__device__ float2   g_Kf[HDIM * 8193];                  // rfft(k, 16384) per h
__device__ uint32_t g_P[(size_t)BDIM * HDIM * LDIM];    // gelu result, fp16 (h, h) duplicated
__device__ uint32_t g_Wp[HDIM * HDIM];                  // W fp16 (hi, lo) split

__device__ __forceinline__ float2 cmulf2(float2 a, float2 b) {
    return make_float2(a.x * b.x - a.y * b.y, a.x * b.y + a.y * b.x);
}
__device__ __forceinline__ float2 caddf2(float2 a, float2 b) { return make_float2(a.x + b.x, a.y + b.y); }
__device__ __forceinline__ float2 csubf2(float2 a, float2 b) { return make_float2(a.x - b.x, a.y - b.y); }
__device__ __forceinline__ float2 conjf2(float2 a) { return make_float2(a.x, -a.y); }
__device__ __forceinline__ int rev13(int k) { return (int)(__brev((unsigned)k) >> 19); }

__device__ __forceinline__ uint32_t pack_w(float v) {
    __half h = __float2half_rn(v);
    __half l = __float2half_rn(v - __half2float(h));
    return (uint32_t)__half_as_ushort(h) | ((uint32_t)__half_as_ushort(l) << 16);
}
__device__ __forceinline__ uint32_t pack_g(float v) {
    uint32_t h = (uint32_t)__half_as_ushort(__float2half_rn(v));
    return h | (h << 16);
}

// Fused first forward pass computed directly from global input (upper half zero):
// pass s=0 butterfly with a2=a3=0. Thread handles g in [0,2048).
__device__ __forceinline__ void load_pass1(float2* A, const float2* up, int tid) {
#pragma unroll
    for (int p = 0; p < 4; p++) {
        int g = tid + p * 512;
        float2 a0 = up[g];
        float2 a1 = up[g + 2048];
        float ang = (-6.283185307179586f / 8192.0f) * (float)g;
        float sn, cs; __sincosf(ang, &sn, &cs);
        float2 w1 = make_float2(cs, sn);
        float2 w2 = cmulf2(w1, w1);
        A[g]        = caddf2(a0, a1);
        A[g + 2048] = cmulf2(csubf2(a0, a1), w2);
        float2 m  = make_float2(a0.x + a1.y, a0.y - a1.x);   // a0 - i*a1
        A[g + 4096] = cmulf2(m, w1);
        float2 pq = make_float2(a0.x - a1.y, a0.y + a1.x);   // a0 + i*a1
        A[g + 6144] = cmulf2(cmulf2(pq, w1), w2);
    }
}

// Remaining fused double radix-2 DIF passes (s=2..10) + final radix-2.
__device__ void fft_forward_rest(float2* A, int tid) {
#pragma unroll
    for (int s = 2; s < 12; s += 2) {
        int ld2 = 11 - s;
        int d2 = 1 << ld2;
        int d1 = d2 << 1;
        __syncthreads();
#pragma unroll
        for (int p = 0; p < 4; p++) {
            int g = tid + p * 512;
            int tw = g & (d2 - 1);
            int i = ((g >> ld2) << (ld2 + 2)) + tw;
            float2 a0 = A[i], a1 = A[i + d2], a2 = A[i + d1], a3 = A[i + d1 + d2];
            float ang = (-6.283185307179586f / 8192.0f) * (float)(tw << s);
            float sn, cs; __sincosf(ang, &sn, &cs);
            float2 w1 = make_float2(cs, sn);
            float2 w2 = cmulf2(w1, w1);
            float2 s02 = caddf2(a0, a2), d02 = csubf2(a0, a2);
            float2 s13 = caddf2(a1, a3), d13 = csubf2(a1, a3);
            A[i]      = caddf2(s02, s13);
            A[i + d2] = cmulf2(csubf2(s02, s13), w2);
            float2 m  = make_float2(d02.x + d13.y, d02.y - d13.x);
            A[i + d1] = cmulf2(m, w1);
            float2 pq = make_float2(d02.x - d13.y, d02.y + d13.x);
            A[i + d1 + d2] = cmulf2(cmulf2(pq, w1), w2);
        }
    }
    __syncthreads();
#pragma unroll
    for (int p = 0; p < 8; p++) {
        int j = tid + p * 512;
        float2 a = A[2 * j], b = A[2 * j + 1];
        A[2 * j]     = caddf2(a, b);
        A[2 * j + 1] = csubf2(a, b);
    }
    __syncthreads();
}

// Fused double radix-2 DIT passes (conjugate twiddles): bit-reversed -> natural.
__device__ void fft_inverse(float2* A, int tid) {
    __syncthreads();
#pragma unroll
    for (int p = 0; p < 8; p++) {
        int j = tid + p * 512;
        float2 a = A[2 * j], b = A[2 * j + 1];
        A[2 * j]     = caddf2(a, b);
        A[2 * j + 1] = csubf2(a, b);
    }
#pragma unroll
    for (int s = 1; s < 13; s += 2) {
        int d1 = 1 << s;
        int d2 = d1 << 1;
        __syncthreads();
#pragma unroll
        for (int p = 0; p < 4; p++) {
            int g = tid + p * 512;
            int tw = g & (d1 - 1);
            int i = ((g >> s) << (s + 2)) + tw;
            float2 a0 = A[i], a1 = A[i + d1], a2 = A[i + d2], a3 = A[i + d1 + d2];
            float ang = (6.283185307179586f / 8192.0f) * (float)(tw << (11 - s));
            float sn, cs; __sincosf(ang, &sn, &cs);
            float2 v0 = make_float2(cs, sn);
            float2 w  = cmulf2(v0, v0);
            float2 t1 = cmulf2(a1, w);
            float2 t3 = cmulf2(a3, w);
            float2 b0 = caddf2(a0, t1), b1 = csubf2(a0, t1);
            float2 b2 = caddf2(a2, t3), b3 = csubf2(a2, t3);
            float2 e  = cmulf2(b2, v0);
            float2 f  = cmulf2(b3, v0);
            A[i]           = caddf2(b0, e);
            A[i + d2]      = csubf2(b0, e);
            A[i + d1]      = make_float2(b1.x - f.y, b1.y + f.x);
            A[i + d1 + d2] = make_float2(b1.x + f.y, b1.y - f.x);
        }
    }
    __syncthreads();
}

// Kernel A: Kf[h] = rfft(k[h], 16384)
extern "C" __global__ void __launch_bounds__(512) kf_kernel(const float* __restrict__ kin) {
    extern __shared__ float2 sh[];
    float2* A = sh;
    int tid = threadIdx.x;
    int h = blockIdx.x;
    const float2* kp = (const float2*)(kin + (size_t)h * LDIM);
    load_pass1(A, kp, tid);
    fft_forward_rest(A, tid);
    float2* outp = g_Kf + (size_t)h * 8193;
    for (int k = tid; k < MH; k += 512) {
        if (k == 0) {
            float2 Z0 = A[0];
            outp[0]    = make_float2(Z0.x + Z0.y, 0.f);
            outp[8192] = make_float2(Z0.x - Z0.y, 0.f);
            outp[4096] = conjf2(A[1]);
        } else {
            float2 Zk = A[rev13(k)];
            float2 Zm = A[rev13(MFFT - k)];
            float2 cZm = conjf2(Zm);
            float2 E  = make_float2(0.5f * (Zk.x + cZm.x), 0.5f * (Zk.y + cZm.y));
            float2 Dd = csubf2(Zk, cZm);
            float2 O  = make_float2(0.5f * Dd.y, -0.5f * Dd.x);
            float ang = (-3.14159265358979323846f / 8192.0f) * (float)k;
            float sn, cs; __sincosf(ang, &sn, &cs);
            float2 Wt = make_float2(cs, sn);
            float2 WO = cmulf2(Wt, O);
            outp[k]        = caddf2(E, WO);
            outp[MFFT - k] = conjf2(csubf2(E, WO));
        }
    }
}

// Kernel B: conv + skip + gelu -> fp16 (h,h) words
extern "C" __global__ void __launch_bounds__(512) conv_kernel(
    const float* __restrict__ u, const float* __restrict__ Dv) {
    extern __shared__ float2 sh[];
    float2* A = sh;
    int tid = threadIdx.x;
    int b = blockIdx.x & (BDIM - 1);
    int h = blockIdx.x >> 3;
    const float2* up = (const float2*)(u + ((size_t)b * HDIM + h) * LDIM);
    load_pass1(A, up, tid);
    fft_forward_rest(A, tid);

    const float2* Kf = g_Kf + (size_t)h * 8193;
    for (int k = tid; k < MH; k += 512) {
        if (k == 0) {
            float2 Z0 = A[0];
            float X0 = Z0.x + Z0.y;
            float XM = Z0.x - Z0.y;
            float2 K0 = Kf[0], KM = Kf[8192];
            float2 Y0 = make_float2(X0 * K0.x, X0 * K0.y);
            float2 YM = make_float2(XM * KM.x, XM * KM.y);
            float2 cYM = conjf2(YM);
            float2 Ep = make_float2(0.5f * (Y0.x + cYM.x), 0.5f * (Y0.y + cYM.y));
            float2 Op = make_float2(0.5f * (Y0.x - cYM.x), 0.5f * (Y0.y - cYM.y));
            A[0] = make_float2(Ep.x - Op.y, Ep.y + Op.x);
            float2 Zq = A[1];
            float2 Yq = cmulf2(conjf2(Zq), Kf[4096]);
            A[1] = conjf2(Yq);
        } else {
            int rk = rev13(k), rm = rev13(MFFT - k);
            float2 Zk = A[rk], Zm = A[rm];
            float2 cZm = conjf2(Zm);
            float2 E  = make_float2(0.5f * (Zk.x + cZm.x), 0.5f * (Zk.y + cZm.y));
            float2 Dd = csubf2(Zk, cZm);
            float2 O  = make_float2(0.5f * Dd.y, -0.5f * Dd.x);
            float ang = (-3.14159265358979323846f / 8192.0f) * (float)k;
            float sn, cs; __sincosf(ang, &sn, &cs);
            float2 Wt = make_float2(cs, sn);
            float2 WO = cmulf2(Wt, O);
            float2 Xk = caddf2(E, WO);
            float2 Xm = conjf2(csubf2(E, WO));
            float2 Yk = cmulf2(Xk, Kf[k]);
            float2 Ym = cmulf2(Xm, Kf[MFFT - k]);
            float2 cYm = conjf2(Ym);
            float2 Ep = make_float2(0.5f * (Yk.x + cYm.x), 0.5f * (Yk.y + cYm.y));
            float2 P  = make_float2(0.5f * (Yk.x - cYm.x), 0.5f * (Yk.y - cYm.y));
            float2 Op = cmulf2(conjf2(Wt), P);
            A[rk] = make_float2(Ep.x - Op.y, Ep.y + Op.x);
            A[rm] = make_float2(Ep.x + Op.y, Op.x - Ep.y);
        }
    }
    fft_inverse(A, tid);

    float Dh = Dv[h];
    uint2* gp = (uint2*)(g_P + ((size_t)b * HDIM + h) * LDIM);
    const float inv = 1.0f / (float)MFFT;
    for (int j = tid; j < MH; j += 512) {
        float2 z = A[j];
        float2 uu = up[j];
        float y0 = z.x * inv + Dh * uu.x;
        float y1 = z.y * inv + Dh * uu.y;
        float g0 = 0.5f * y0 * (1.0f + erff(y0 * 0.70710678118654752440f));
        float g1 = 0.5f * y1 * (1.0f + erff(y1 * 0.70710678118654752440f));
        gp[j] = make_uint2(pack_g(g0), pack_g(g1));
    }
}

// W pack kernel
extern "C" __global__ void __launch_bounds__(256) wpack_kernel(const float* __restrict__ Wm) {
    int i = blockIdx.x * 256 + threadIdx.x;
    g_Wp[i] = pack_w(Wm[i]);
}

// ---------------- mma.sync GEMM, 3-stage cp.async pipeline (R7, kept) ----------------
__device__ __forceinline__ uint32_t smem_u32(const void* p) {
    return (uint32_t)__cvta_generic_to_shared(p);
}
__device__ __forceinline__ uint32_t swz(uint32_t off) { return off ^ ((off >> 3) & 0x70); }

__device__ __forceinline__ void ldmat4(uint32_t* r, uint32_t addr) {
    asm volatile("ldmatrix.sync.aligned.m8n8.x4.shared.b16 {%0,%1,%2,%3}, [%4];"
                 : "=r"(r[0]), "=r"(r[1]), "=r"(r[2]), "=r"(r[3]) : "r"(addr));
}
__device__ __forceinline__ void mma16816(float* d, const uint32_t* a, uint32_t b0, uint32_t b1) {
    asm volatile(
        "mma.sync.aligned.m16n8k16.row.col.f32.f16.f16.f32 "
        "{%0,%1,%2,%3}, {%4,%5,%6,%7}, {%8,%9}, {%0,%1,%2,%3};"
        : "+f"(d[0]), "+f"(d[1]), "+f"(d[2]), "+f"(d[3])
        : "r"(a[0]), "r"(a[1]), "r"(a[2]), "r"(a[3]), "r"(b0), "r"(b1));
}
#define CP16(dst, src) asm volatile("cp.async.cg.shared.global [%0], [%1], 16;" :: "r"(dst), "l"(src) : "memory")
#define CP4(dst, src)  asm volatile("cp.async.ca.shared.global [%0], [%1], 4;"  :: "r"(dst), "l"(src) : "memory")
#define CP_COMMIT()    asm volatile("cp.async.commit_group;" ::: "memory")
#define CP_WAIT1()     asm volatile("cp.async.wait_group 1;" ::: "memory")

extern "C" __global__ void __launch_bounds__(256, 2) gemm_mma_kernel(
    const float* __restrict__ bias, float* __restrict__ outp) {
    extern __shared__ char smem[];
    uint32_t sb = smem_u32(smem);
    int t = threadIdx.x;
    int lane = t & 31, wid = t >> 5;
    int warp_m = wid >> 2, warp_n = wid & 3;   // 2 x 4 warp grid; warp tile 64x32
    int o0 = blockIdx.x * 128, l0 = blockIdx.y * 128, b = blockIdx.z;

    int a_row = t >> 1, a_half = t & 1;
    const uint32_t* wp = g_Wp + (size_t)(o0 + a_row) * HDIM + a_half * 16;
    int b_l = t & 127, b_hg = (t >> 7) * 16;
    const uint32_t* gpB = g_P + (size_t)b * HDIM * LDIM + l0 + b_l;

    auto load_chunk = [&](int c) {
        int buf = c % 3;
        uint32_t sA = sb + buf * 32768;
        uint32_t sB = sA + 16384;
        const uint32_t* aw = wp + c * 32;
#pragma unroll
        for (int j = 0; j < 4; j++) {
            uint32_t off = (uint32_t)(a_row * 128 + (a_half * 16 + j * 4) * 4);
            CP16(sA + swz(off), aw + j * 4);
        }
#pragma unroll
        for (int q = 0; q < 16; q++) {
            int hw = b_hg + q;
            uint32_t off = (uint32_t)(b_l * 128 + hw * 4);
            CP4(sB + swz(off), gpB + (size_t)(c * 32 + hw) * LDIM);
        }
    };

    int a_lrow = (lane & 7) + ((lane >> 3) & 1) * 8;
    int a_lcol = (lane >> 4) * 16;
    int b_lrow = (lane & 7) + ((lane >> 4) & 1) * 8;
    int b_lcol = ((lane >> 3) & 1) * 16;
    uint32_t xorm = (uint32_t)((lane & 7) << 4);

    float acc[4][4][4];
#pragma unroll
    for (int i = 0; i < 4; i++)
#pragma unroll
        for (int j = 0; j < 4; j++)
#pragma unroll
            for (int q = 0; q < 4; q++) acc[i][j][q] = 0.f;

    load_chunk(0);
    CP_COMMIT();
    load_chunk(1);
    CP_COMMIT();

#pragma unroll 1
    for (int c = 0; c < 16; c++) {
        CP_WAIT1();
        __syncthreads();
        if (c + 2 < 16) load_chunk(c + 2);
        CP_COMMIT();
        int buf = c % 3;
        uint32_t sA = sb + buf * 32768;
        uint32_t sB = sA + 16384;
#pragma unroll
        for (int s = 0; s < 4; s++) {
            uint32_t afr[4][4];
#pragma unroll
            for (int mt = 0; mt < 4; mt++) {
                uint32_t off = (uint32_t)((warp_m * 64 + mt * 16 + a_lrow) * 128 + s * 32 + a_lcol);
                ldmat4(afr[mt], sA + (off ^ xorm));
            }
#pragma unroll
            for (int bt = 0; bt < 2; bt++) {
                uint32_t bfr[4];
                uint32_t off = (uint32_t)((warp_n * 32 + bt * 16 + b_lrow) * 128 + s * 32 + b_lcol);
                ldmat4(bfr, sB + (off ^ xorm));
#pragma unroll
                for (int mt = 0; mt < 4; mt++) {
                    mma16816(acc[mt][bt * 2 + 0], afr[mt], bfr[0], bfr[1]);
                    mma16816(acc[mt][bt * 2 + 1], afr[mt], bfr[2], bfr[3]);
                }
            }
        }
    }

#pragma unroll
    for (int mt = 0; mt < 4; mt++) {
        int r = o0 + warp_m * 64 + mt * 16 + (lane >> 2);
        float bs0 = bias[r], bs1 = bias[r + 8];
        float* p0 = outp + ((size_t)b * HDIM + r) * LDIM + l0 + warp_n * 32 + (lane & 3) * 2;
        float* p1 = p0 + 8 * LDIM;
#pragma unroll
        for (int nt = 0; nt < 4; nt++) {
            float2 v0 = make_float2(acc[mt][nt][0] + bs0, acc[mt][nt][1] + bs0);
            float2 v1 = make_float2(acc[mt][nt][2] + bs1, acc[mt][nt][3] + bs1);
            *(float2*)(p0 + nt * 8) = v0;
            *(float2*)(p1 + nt * 8) = v1;
        }
    }
}

extern "C" void kernel_launch(void* const* d_in, const int* in_sizes, int n_in,
                              void* d_out, int out_size) {
    const float* u    = (const float*)d_in[0];   // (8,512,8192)
    const float* kin  = (const float*)d_in[1];   // (1,512,8192)
    const float* Dv   = (const float*)d_in[2];   // (1,512)
    const float* Wm   = (const float*)d_in[3];   // (512,512)
    const float* bias = (const float*)d_in[4];   // (512,)
    float* outp = (float*)d_out;                 // (8,512,8192)

    size_t smem = (size_t)MFFT * sizeof(float2);  // 64 KB (unpadded, R6 schedule)
    cudaFuncSetAttribute(kf_kernel,   cudaFuncAttributeMaxDynamicSharedMemorySize, (int)smem);
    cudaFuncSetAttribute(conv_kernel, cudaFuncAttributeMaxDynamicSharedMemorySize, (int)smem);
    size_t gsmem = 3 * 32768;                      // 96 KB (3-stage)
    cudaFuncSetAttribute(gemm_mma_kernel, cudaFuncAttributeMaxDynamicSharedMemorySize, (int)gsmem);

    wpack_kernel<<<HDIM * HDIM / 256, 256>>>(Wm);
    kf_kernel<<<HDIM, 512, smem>>>(kin);
    conv_kernel<<<BDIM * HDIM, 512, smem>>>(u, Dv);
    dim3 grid(HDIM / 128, LDIM / 128, BDIM);      // o fastest -> B-panel L2 reuse
    gemm_mma_kernel<<<grid, 256, gsmem>>>(bias, outp);
}